// round 3
// baseline (speedup 1.0000x reference)
#include <cuda_runtime.h>
#include <cuda_fp16.h>
#include <cuda_bf16.h>

// ---------------------------------------------------------------------------
// Problem constants
// ---------------------------------------------------------------------------
#define NXg 256
#define NBg 256
#define NK  64
#define NMAX 65536
#define NBINS 65536

static __device__ __constant__ float c_E2[8] = {
    4.0f/9.0f, 1.0f/9.0f, 1.0f/9.0f, 4.0f/9.0f,
    4.0f/9.0f, 1.0f/9.0f, 1.0f/9.0f, 4.0f/9.0f
};

#define LXMIN_D (-9.210340371976182)   /* log(1e-4) */
#define LBMIN_D (-6.907755278982137)   /* log(1e-3) */
#define LBMAX_D ( 3.912023005428146)   /* log(50)   */

// ---------------------------------------------------------------------------
// Device scratch (all static — no allocation)
// ---------------------------------------------------------------------------
__device__ __half g_pdf_h[NXg * NBg * 8];   // [i][j][f], E2 baked in
__device__ __half g_ff_h [NXg * NBg * 8];   // [i][j][f]
__device__ float  g_fnpc[3];
__device__ int    g_hist[NBINS];            // zero-init; re-zeroed by scatter
__device__ int    g_off [NBINS];
__device__ int    g_bsum[256];
__device__ int    g_bpref[256];
__device__ unsigned short g_keys[NMAX];
__device__ int    g_perm[NMAX];

__device__ __forceinline__ float4 lerp4(float4 a, float4 b, float t) {
    float4 r;
    r.x = fmaf(t, b.x - a.x, a.x);
    r.y = fmaf(t, b.y - a.y, a.y);
    r.z = fmaf(t, b.z - a.z, a.z);
    r.w = fmaf(t, b.w - a.w, a.w);
    return r;
}

// uint4 (8 halves = one column's 8 flavors) -> two float4
__device__ __forceinline__ void h8_to_f(uint4 v, float4& a, float4& b) {
    const __half2* h = reinterpret_cast<const __half2*>(&v);
    float2 f0 = __half22float2(h[0]);
    float2 f1 = __half22float2(h[1]);
    float2 f2 = __half22float2(h[2]);
    float2 f3 = __half22float2(h[3]);
    a = make_float4(f0.x, f0.y, f1.x, f1.y);
    b = make_float4(f2.x, f2.y, f3.x, f3.y);
}

// ---------------------------------------------------------------------------
// Kernel 1: transpose grids to [i][j][f] fp16 (E2 baked into pdf),
// compute per-event sort key + histogram, and fnp uniforms.
// 65536 threads.
// ---------------------------------------------------------------------------
__global__ __launch_bounds__(256)
void prep_kernel(const float* __restrict__ pdf,
                 const float* __restrict__ ff,
                 const float* __restrict__ ev,
                 const float* __restrict__ fnp,
                 int n_events)
{
    int ij = blockIdx.x * blockDim.x + threadIdx.x;

    if (ij == 0) {
        float p0 = fnp[0], p1 = fnp[1], p2 = fnp[2], p3 = fnp[3];
        float lam_p = log1pf(__expf(p0));
        float lam_f = log1pf(__expf(p1));
        float sig2  = __fdividef(1.0f, 1.0f + __expf(-p2));
        float sig3  = __fdividef(1.0f, 1.0f + __expf(-p3));
        g_fnpc[0] = lam_p;
        g_fnpc[1] = lam_p * sig2;
        g_fnpc[2] = lam_f * (1.0f + sig3);
    }

    if (ij < NXg * NBg) {
        union { uint4 u; __half h[8]; } pk, fk;
#pragma unroll
        for (int f = 0; f < 8; f++) {
            pk.h[f] = __float2half_rn(c_E2[f] * pdf[f * (NXg * NBg) + ij]);
            fk.h[f] = __float2half_rn(ff[f * (NXg * NBg) + ij]);
        }
        reinterpret_cast<uint4*>(g_pdf_h)[ij] = pk.u;
        reinterpret_cast<uint4*>(g_ff_h )[ij] = fk.u;
    }

    // per-event sort key: (i0f:6 | qT-bucket:3 | i0p:7) = 16 bits
    if (ij < n_events && ij < NMAX) {
        const float LXMIN  = (float)LXMIN_D;
        const float XSCALE = (float)(255.0 / (0.0 - LXMIN_D));
        float4 e = reinterpret_cast<const float4*>(ev)[ij];
        float x = e.x, PhT = e.y, z = e.w;
        float lx = __logf(x);
        float lz = __logf(z);
        float lqT = __logf(PhT) - lz;

        float fx = fminf(fmaxf((lx - LXMIN) * XSCALE, 0.0f), 255.0f - 1e-4f);
        float fz = fminf(fmaxf((lz - LXMIN) * XSCALE, 0.0f), 255.0f - 1e-4f);
        int i0p = (int)fx;
        int i0f = (int)fz;

        int kp = min(max(i0p - 128, 0), 127);
        int kf = min(max(i0f - 192, 0), 63);
        int kq = min(max((int)((lqT + 2.3f) * 2.85f), 0), 7);

        unsigned short key = (unsigned short)((kf << 10) | (kq << 7) | kp);
        g_keys[ij] = key;
        atomicAdd(&g_hist[key], 1);
    }
}

// ---------------------------------------------------------------------------
// Kernel 2/3: two-level exclusive scan of the 65536-bin histogram.
// ---------------------------------------------------------------------------
__global__ __launch_bounds__(256)
void scan1_kernel()
{
    __shared__ int sm[256];
    int b = blockIdx.x, t = threadIdx.x;
    int v = g_hist[b * 256 + t];
    sm[t] = v; __syncthreads();
#pragma unroll
    for (int o = 1; o < 256; o <<= 1) {
        int x = (t >= o) ? sm[t - o] : 0;
        __syncthreads();
        sm[t] += x;
        __syncthreads();
    }
    g_off[b * 256 + t] = sm[t] - v;        // exclusive within block
    if (t == 255) g_bsum[b] = sm[255];
}

__global__ __launch_bounds__(256)
void scan2_kernel()
{
    __shared__ int sm[256];
    int t = threadIdx.x;
    int v = g_bsum[t];
    sm[t] = v; __syncthreads();
#pragma unroll
    for (int o = 1; o < 256; o <<= 1) {
        int x = (t >= o) ? sm[t - o] : 0;
        __syncthreads();
        sm[t] += x;
        __syncthreads();
    }
    g_bpref[t] = sm[t] - v;
}

// ---------------------------------------------------------------------------
// Kernel 4: scatter event indices into sorted order; re-zero hist for the
// next graph replay.
// ---------------------------------------------------------------------------
__global__ __launch_bounds__(256)
void scatter_kernel(int n_events)
{
    int n = blockIdx.x * blockDim.x + threadIdx.x;
    if (n < n_events && n < NMAX) {
        int key = g_keys[n];
        int pos = g_bpref[key >> 8] + atomicAdd(&g_off[key], 1);
        g_perm[pos] = n;
    }
    if (n < NBINS) g_hist[n] = 0;
}

// ---------------------------------------------------------------------------
// Kernel 5: main — 2 lanes per event over sorted order.
// ---------------------------------------------------------------------------
__global__ __launch_bounds__(256)
void sidis_kernel(const float* __restrict__ ev,
                  const float* __restrict__ ogx,
                  const float* __restrict__ ogw,
                  float* __restrict__ out,
                  int n_events)
{
    __shared__ float s_u[NK], s_lu[NK], s_w[NK];
    int t = threadIdx.x;
    if (t < NK) {
        float u = ogx[t];
        s_u[t]  = u;
        s_lu[t] = __logf(u);
        s_w[t]  = ogw[t];
    }
    __syncthreads();

    int gt  = blockIdx.x * blockDim.x + t;
    int p   = gt >> 1;
    int sub = gt & 1;
    bool valid = (p < n_events);
    if (!valid) p = n_events - 1;
    int n = g_perm[p];

    const float LXMIN  = (float)LXMIN_D;
    const float LBMIN  = (float)LBMIN_D;
    const float XSCALE = (float)(255.0 / (0.0 - LXMIN_D));
    const float BSCALE = (float)(255.0 / (LBMAX_D - LBMIN_D));

    float4 e = __ldg(reinterpret_cast<const float4*>(ev) + n);
    float x = e.x, PhT = e.y, Q = e.z, z = e.w;

    float rz  = __fdividef(1.0f, z);
    float rP  = __fdividef(1.0f, PhT);
    float qT     = PhT * rz;
    float inv_qT = z * rP;
    float inv_z2 = rz * rz;
    float Q2  = Q * Q;

    float lx = __logf(x);
    float fx = fminf(fmaxf((lx - LXMIN) * XSCALE, 0.0f), 255.0f - 1e-4f);
    int   i0p = (int)fx;
    float txp = fx - (float)i0p;

    float lz = __logf(z);
    float fz = fminf(fmaxf((lz - LXMIN) * XSCALE, 0.0f), 255.0f - 1e-4f);
    int   i0f = (int)fz;
    float txf = fz - (float)i0f;

    float lQ2 = 2.0f * __logf(Q);
    float log_invqT = lz - __logf(PhT);

    float A = g_fnpc[0], B = g_fnpc[1], C = g_fnpc[2];
    float c = fmaf(0.12f, lQ2, A) - B * lx + C * inv_z2;

    float cq = c * inv_qT * inv_qT;
    float u0 = s_u[0];
    float arg_cut = fmaf(-cq, u0 * u0, -36.0f);

    const __half* pbase = g_pdf_h + i0p * (NBg * 8);
    const __half* fbase = g_ff_h  + i0f * (NBg * 8);

    float acc = 0.0f;
    for (int k = sub; k < NK; k += 2) {
        float u   = s_u[k];
        float arg = -cq * u * u;
        if (arg < arg_cut) break;

        float lb = s_lu[k] + log_invqT;
        float fb = fminf(fmaxf((lb - LBMIN) * BSCALE, 0.0f), 255.0f - 1e-4f);
        int   j0 = (int)fb;
        float tb = fb - (float)j0;

        // pdf: rows i0p, i0p+1; 8 LDG.128 total across both grids
        const uint4* pr0 = reinterpret_cast<const uint4*>(pbase + j0 * 8);
        const uint4* pr1 = reinterpret_cast<const uint4*>(pbase + NBg * 8 + j0 * 8);
        uint4 P00 = __ldg(pr0), P01 = __ldg(pr0 + 1);
        uint4 P10 = __ldg(pr1), P11 = __ldg(pr1 + 1);

        const uint4* fr0 = reinterpret_cast<const uint4*>(fbase + j0 * 8);
        const uint4* fr1 = reinterpret_cast<const uint4*>(fbase + NBg * 8 + j0 * 8);
        uint4 F00 = __ldg(fr0), F01 = __ldg(fr0 + 1);
        uint4 F10 = __ldg(fr1), F11 = __ldg(fr1 + 1);

        float4 pa0, pa1, pb0, pb1, pc0, pc1, pd0, pd1;
        h8_to_f(P00, pa0, pa1);  h8_to_f(P01, pb0, pb1);
        h8_to_f(P10, pc0, pc1);  h8_to_f(P11, pd0, pd1);

        float4 fa0, fa1, fb0, fb1, fc0, fc1, fd0, fd1;
        h8_to_f(F00, fa0, fa1);  h8_to_f(F01, fb0, fb1);
        h8_to_f(F10, fc0, fc1);  h8_to_f(F11, fd0, fd1);

        float4 pr0l = lerp4(pa0, pb0, tb);
        float4 pr0h = lerp4(pa1, pb1, tb);
        float4 pr1l = lerp4(pc0, pd0, tb);
        float4 pr1h = lerp4(pc1, pd1, tb);
        float4 pvl  = lerp4(pr0l, pr1l, txp);
        float4 pvh  = lerp4(pr0h, pr1h, txp);

        float4 fr0l = lerp4(fa0, fb0, tb);
        float4 fr0h = lerp4(fa1, fb1, tb);
        float4 fr1l = lerp4(fc0, fd0, tb);
        float4 fr1h = lerp4(fc1, fd1, tb);
        float4 fvl  = lerp4(fr0l, fr1l, txf);
        float4 fvh  = lerp4(fr0h, fr1h, txf);

        float s = pvl.x * fvl.x + pvl.y * fvl.y + pvl.z * fvl.z + pvl.w * fvl.w
                + pvh.x * fvh.x + pvh.y * fvh.y + pvh.z * fvh.z + pvh.w * fvh.w;

        acc = fmaf(s * s_w[k], __expf(arg), acc);
    }

    // reduce the 2 lanes of this event
    acc += __shfl_xor_sync(0xFFFFFFFFu, acc, 1);

    if (sub == 0 && valid) {
        float FUUT = acc * inv_qT * inv_qT;

        const float ALPHA0 = 0.00729735253f;
        const float L_ME2  = 15.1582899f;
        float rx = __fdividef(1.0f, x);
        float rQ = __fdividef(1.0f, Q);
        float lQme = lQ2 + L_ME2;
        float alpha = __fdividef(ALPHA0,
                      1.0f - (ALPHA0 / (3.0f * 3.14159265358979f)) * lQme);
        float gamma = 2.0f * 0.8803f * x * rQ;
        float y  = Q2 * rx * (1.0f / (140.0f - 0.8803f));
        float g2y2 = gamma * gamma * y * y;
        float epsn = 1.0f - y - 0.25f * g2y2;
        float epsd = 1.0f - y + 0.5f * y * y + 0.25f * g2y2;
        float eps  = __fdividef(epsn, epsd);
        float pre = 78.9568352f
                  * alpha * alpha * (z * z) * qT
                  * rx * (rQ * rQ * rQ)
                  * (y * y) * 0.5f * __fdividef(1.0f, 1.0f - eps)
                  * (1.0f + gamma * gamma * (0.5f * rx));

        out[n] = pre * FUUT;
    }
}

// ---------------------------------------------------------------------------
// kernel_launch
// Inputs: events (N,4), pdf (8,256,256), ff (8,256,256), ogata_x (64),
// ogata_w (64), fnp (4)
// ---------------------------------------------------------------------------
extern "C" void kernel_launch(void* const* d_in, const int* in_sizes, int n_in,
                              void* d_out, int out_size)
{
    const float* ev   = (const float*)d_in[0];
    const float* pdfg = (const float*)d_in[1];
    const float* ffg  = (const float*)d_in[2];
    const float* ogx  = (const float*)d_in[3];
    const float* ogw  = (const float*)d_in[4];
    const float* fnp  = (const float*)d_in[5];
    float* out = (float*)d_out;

    int n_events = in_sizes[0] / 4;

    prep_kernel<<<256, 256>>>(pdfg, ffg, ev, fnp, n_events);
    scan1_kernel<<<256, 256>>>();
    scan2_kernel<<<1, 256>>>();
    scatter_kernel<<<256, 256>>>(n_events);

    int total_threads = n_events * 2;
    int blocks = (total_threads + 255) / 256;
    sidis_kernel<<<blocks, 256>>>(ev, ogx, ogw, out, n_events);
}

// round 4
// speedup vs baseline: 1.4268x; 1.4268x over previous
#include <cuda_runtime.h>
#include <cuda_fp16.h>
#include <cuda_bf16.h>

// ---------------------------------------------------------------------------
// Problem constants
// ---------------------------------------------------------------------------
#define NXg 256
#define NBg 256
#define NK  64

static __device__ __constant__ float c_E2[8] = {
    4.0f/9.0f, 1.0f/9.0f, 1.0f/9.0f, 4.0f/9.0f,
    4.0f/9.0f, 1.0f/9.0f, 1.0f/9.0f, 4.0f/9.0f
};

#define LXMIN_D (-9.210340371976182)   /* log(1e-4) */
#define LBMIN_D (-6.907755278982137)   /* log(1e-3) */
#define LBMAX_D ( 3.912023005428146)   /* log(50)   */

// ---------------------------------------------------------------------------
// Device scratch (static — no allocation)
// ---------------------------------------------------------------------------
__device__ __half g_pdf_h[NXg * NBg * 8];   // [i][j][f], E2 baked in
__device__ __half g_ff_h [NXg * NBg * 8];   // [i][j][f]
__device__ float  g_fnpc[3];

__device__ __forceinline__ float4 lerp4(float4 a, float4 b, float t) {
    float4 r;
    r.x = fmaf(t, b.x - a.x, a.x);
    r.y = fmaf(t, b.y - a.y, a.y);
    r.z = fmaf(t, b.z - a.z, a.z);
    r.w = fmaf(t, b.w - a.w, a.w);
    return r;
}

// uint4 (8 halves = one column's 8 flavors) -> two float4
__device__ __forceinline__ void h8_to_f(uint4 v, float4& a, float4& b) {
    const __half2* h = reinterpret_cast<const __half2*>(&v);
    float2 f0 = __half22float2(h[0]);
    float2 f1 = __half22float2(h[1]);
    float2 f2 = __half22float2(h[2]);
    float2 f3 = __half22float2(h[3]);
    a = make_float4(f0.x, f0.y, f1.x, f1.y);
    b = make_float4(f2.x, f2.y, f3.x, f3.y);
}

// ---------------------------------------------------------------------------
// Kernel 1: transpose grids to [i][j][f] fp16 (E2 baked into pdf) + fnp
// uniforms. 65536 threads, one per grid cell.
// ---------------------------------------------------------------------------
__global__ __launch_bounds__(256)
void prep_kernel(const float* __restrict__ pdf,
                 const float* __restrict__ ff,
                 const float* __restrict__ fnp)
{
    int ij = blockIdx.x * blockDim.x + threadIdx.x;

    if (ij == 0) {
        float p0 = fnp[0], p1 = fnp[1], p2 = fnp[2], p3 = fnp[3];
        float lam_p = log1pf(__expf(p0));
        float lam_f = log1pf(__expf(p1));
        float sig2  = __fdividef(1.0f, 1.0f + __expf(-p2));
        float sig3  = __fdividef(1.0f, 1.0f + __expf(-p3));
        g_fnpc[0] = lam_p;
        g_fnpc[1] = lam_p * sig2;
        g_fnpc[2] = lam_f * (1.0f + sig3);
    }

    if (ij < NXg * NBg) {
        union { uint4 u; __half h[8]; } pk, fk;
#pragma unroll
        for (int f = 0; f < 8; f++) {
            pk.h[f] = __float2half_rn(c_E2[f] * pdf[f * (NXg * NBg) + ij]);
            fk.h[f] = __float2half_rn(ff[f * (NXg * NBg) + ij]);
        }
        reinterpret_cast<uint4*>(g_pdf_h)[ij] = pk.u;
        reinterpret_cast<uint4*>(g_ff_h )[ij] = fk.u;
    }
}

// ---------------------------------------------------------------------------
// Kernel 2: main — 2 lanes per event, counted loop (trip count from a
// 6-step binary search over the ascending u^2 table), unrolled by 2.
// ---------------------------------------------------------------------------
__global__ __launch_bounds__(256)
void sidis_kernel(const float* __restrict__ ev,
                  const float* __restrict__ ogx,
                  const float* __restrict__ ogw,
                  float* __restrict__ out,
                  int n_events)
{
    __shared__ float s_u2[NK], s_lu[NK], s_w[NK];
    int t = threadIdx.x;
    if (t < NK) {
        float u = ogx[t];
        s_u2[t] = u * u;
        s_lu[t] = __logf(u);
        s_w[t]  = ogw[t];
    }
    __syncthreads();

    int gt  = blockIdx.x * blockDim.x + t;
    int n   = gt >> 1;          // event index
    int sub = gt & 1;           // 0/1 within event
    if (n >= n_events) return;

    const float LXMIN  = (float)LXMIN_D;
    const float LBMIN  = (float)LBMIN_D;
    const float XSCALE = (float)(255.0 / (0.0 - LXMIN_D));
    const float BSCALE = (float)(255.0 / (LBMAX_D - LBMIN_D));

    float4 e = __ldg(reinterpret_cast<const float4*>(ev) + n);
    float x = e.x, PhT = e.y, Q = e.z, z = e.w;

    float rz  = __fdividef(1.0f, z);
    float rP  = __fdividef(1.0f, PhT);
    float qT     = PhT * rz;
    float inv_qT = z * rP;
    float inv_z2 = rz * rz;
    float Q2  = Q * Q;

    float lx = __logf(x);
    float fx = fminf(fmaxf((lx - LXMIN) * XSCALE, 0.0f), 255.0f - 1e-4f);
    int   i0p = (int)fx;
    float txp = fx - (float)i0p;

    float lz = __logf(z);
    float fz = fminf(fmaxf((lz - LXMIN) * XSCALE, 0.0f), 255.0f - 1e-4f);
    int   i0f = (int)fz;
    float txf = fz - (float)i0f;

    float lQ2 = 2.0f * __logf(Q);
    float log_invqT = lz - __logf(PhT);

    float A = g_fnpc[0], B = g_fnpc[1], C = g_fnpc[2];
    float c = fmaf(0.12f, lQ2, A) - B * lx + C * inv_z2;

    float cq = c * inv_qT * inv_qT;           // arg_k = -cq * u_k^2

    // trip count: number of k with cq*(u_k^2 - u_0^2) <= 36
    float U2 = s_u2[0] + 36.0f * __fdividef(1.0f, cq);
    int kmax = 0;
#pragma unroll
    for (int s = 32; s >= 1; s >>= 1) {
        int m = kmax + s;
        if (m <= NK && s_u2[m - 1] <= U2) kmax = m;
    }

    const __half* pbase = g_pdf_h + i0p * (NBg * 8);
    const __half* fbase = g_ff_h  + i0f * (NBg * 8);

    float acc = 0.0f;
#pragma unroll 2
    for (int k = sub; k < kmax; k += 2) {
        float arg = -cq * s_u2[k];

        float lb = s_lu[k] + log_invqT;
        float fb = fminf(fmaxf((lb - LBMIN) * BSCALE, 0.0f), 255.0f - 1e-4f);
        int   j0 = (int)fb;
        float tb = fb - (float)j0;

        const uint4* pr0 = reinterpret_cast<const uint4*>(pbase + j0 * 8);
        const uint4* pr1 = reinterpret_cast<const uint4*>(pbase + NBg * 8 + j0 * 8);
        uint4 P00 = __ldg(pr0), P01 = __ldg(pr0 + 1);
        uint4 P10 = __ldg(pr1), P11 = __ldg(pr1 + 1);

        const uint4* fr0 = reinterpret_cast<const uint4*>(fbase + j0 * 8);
        const uint4* fr1 = reinterpret_cast<const uint4*>(fbase + NBg * 8 + j0 * 8);
        uint4 F00 = __ldg(fr0), F01 = __ldg(fr0 + 1);
        uint4 F10 = __ldg(fr1), F11 = __ldg(fr1 + 1);

        float4 pa0, pa1, pb0, pb1, pc0, pc1, pd0, pd1;
        h8_to_f(P00, pa0, pa1);  h8_to_f(P01, pb0, pb1);
        h8_to_f(P10, pc0, pc1);  h8_to_f(P11, pd0, pd1);

        float4 fa0, fa1, fb0, fb1, fc0, fc1, fd0, fd1;
        h8_to_f(F00, fa0, fa1);  h8_to_f(F01, fb0, fb1);
        h8_to_f(F10, fc0, fc1);  h8_to_f(F11, fd0, fd1);

        float4 pr0l = lerp4(pa0, pb0, tb);
        float4 pr0h = lerp4(pa1, pb1, tb);
        float4 pr1l = lerp4(pc0, pd0, tb);
        float4 pr1h = lerp4(pc1, pd1, tb);
        float4 pvl  = lerp4(pr0l, pr1l, txp);
        float4 pvh  = lerp4(pr0h, pr1h, txp);

        float4 fr0l = lerp4(fa0, fb0, tb);
        float4 fr0h = lerp4(fa1, fb1, tb);
        float4 fr1l = lerp4(fc0, fd0, tb);
        float4 fr1h = lerp4(fc1, fd1, tb);
        float4 fvl  = lerp4(fr0l, fr1l, txf);
        float4 fvh  = lerp4(fr0h, fr1h, txf);

        float s = pvl.x * fvl.x + pvl.y * fvl.y + pvl.z * fvl.z + pvl.w * fvl.w
                + pvh.x * fvh.x + pvh.y * fvh.y + pvh.z * fvh.z + pvh.w * fvh.w;

        acc = fmaf(s * s_w[k], __expf(arg), acc);
    }

    // reduce the 2 lanes of this event
    acc += __shfl_xor_sync(0xFFFFFFFFu, acc, 1);

    if (sub == 0) {
        float FUUT = acc * inv_qT * inv_qT;

        const float ALPHA0 = 0.00729735253f;
        const float L_ME2  = 15.1582899f;
        float rx = __fdividef(1.0f, x);
        float rQ = __fdividef(1.0f, Q);
        float lQme = lQ2 + L_ME2;
        float alpha = __fdividef(ALPHA0,
                      1.0f - (ALPHA0 / (3.0f * 3.14159265358979f)) * lQme);
        float gamma = 2.0f * 0.8803f * x * rQ;
        float y  = Q2 * rx * (1.0f / (140.0f - 0.8803f));
        float g2y2 = gamma * gamma * y * y;
        float epsn = 1.0f - y - 0.25f * g2y2;
        float epsd = 1.0f - y + 0.5f * y * y + 0.25f * g2y2;
        float eps  = __fdividef(epsn, epsd);
        float pre = 78.9568352f
                  * alpha * alpha * (z * z) * qT
                  * rx * (rQ * rQ * rQ)
                  * (y * y) * 0.5f * __fdividef(1.0f, 1.0f - eps)
                  * (1.0f + gamma * gamma * (0.5f * rx));

        out[n] = pre * FUUT;
    }
}

// ---------------------------------------------------------------------------
// kernel_launch
// Inputs: events (N,4), pdf (8,256,256), ff (8,256,256), ogata_x (64),
// ogata_w (64), fnp (4)
// ---------------------------------------------------------------------------
extern "C" void kernel_launch(void* const* d_in, const int* in_sizes, int n_in,
                              void* d_out, int out_size)
{
    const float* ev   = (const float*)d_in[0];
    const float* pdfg = (const float*)d_in[1];
    const float* ffg  = (const float*)d_in[2];
    const float* ogx  = (const float*)d_in[3];
    const float* ogw  = (const float*)d_in[4];
    const float* fnp  = (const float*)d_in[5];
    float* out = (float*)d_out;

    int n_events = in_sizes[0] / 4;

    prep_kernel<<<(NXg * NBg + 255) / 256, 256>>>(pdfg, ffg, fnp);

    int total_threads = n_events * 2;
    int blocks = (total_threads + 255) / 256;
    sidis_kernel<<<blocks, 256>>>(ev, ogx, ogw, out, n_events);
}

// round 5
// speedup vs baseline: 1.4514x; 1.0173x over previous
#include <cuda_runtime.h>
#include <cuda_fp16.h>
#include <cuda_bf16.h>

// ---------------------------------------------------------------------------
// Problem constants
// ---------------------------------------------------------------------------
#define NXg 256
#define NBg 256
#define NK  64
#define LPE 4

static __device__ __constant__ float c_E2[8] = {
    4.0f/9.0f, 1.0f/9.0f, 1.0f/9.0f, 4.0f/9.0f,
    4.0f/9.0f, 1.0f/9.0f, 1.0f/9.0f, 4.0f/9.0f
};

#define LXMIN_D (-9.210340371976182)   /* log(1e-4) */
#define LBMIN_D (-6.907755278982137)   /* log(1e-3) */
#define LBMAX_D ( 3.912023005428146)   /* log(50)   */

// ---------------------------------------------------------------------------
// Device scratch (static — no allocation)
// ---------------------------------------------------------------------------
__device__ __half g_pdf_h[NXg * NBg * 8];   // [i][j][f], E2 baked in
__device__ __half g_ff_h [NXg * NBg * 8];   // [i][j][f]
__device__ float  g_fnpc[3];
__device__ int    g_kmaxtab[128];           // bucketed conservative trip count

__device__ __forceinline__ float4 lerp4(float4 a, float4 b, float t) {
    float4 r;
    r.x = fmaf(t, b.x - a.x, a.x);
    r.y = fmaf(t, b.y - a.y, a.y);
    r.z = fmaf(t, b.z - a.z, a.z);
    r.w = fmaf(t, b.w - a.w, a.w);
    return r;
}

// uint4 (8 halves = one column's 8 flavors) -> two float4
__device__ __forceinline__ void h8_to_f(uint4 v, float4& a, float4& b) {
    const __half2* h = reinterpret_cast<const __half2*>(&v);
    float2 f0 = __half22float2(h[0]);
    float2 f1 = __half22float2(h[1]);
    float2 f2 = __half22float2(h[2]);
    float2 f3 = __half22float2(h[3]);
    a = make_float4(f0.x, f0.y, f1.x, f1.y);
    b = make_float4(f2.x, f2.y, f3.x, f3.y);
}

// ---------------------------------------------------------------------------
// Kernel 1: transpose grids to [i][j][f] fp16 (E2 baked into pdf),
// fnp uniforms, and the conservative kmax bucket table.
// ---------------------------------------------------------------------------
__global__ __launch_bounds__(256)
void prep_kernel(const float* __restrict__ pdf,
                 const float* __restrict__ ff,
                 const float* __restrict__ ogx,
                 const float* __restrict__ fnp)
{
    int ij = blockIdx.x * blockDim.x + threadIdx.x;

    if (ij == 0) {
        float p0 = fnp[0], p1 = fnp[1], p2 = fnp[2], p3 = fnp[3];
        float lam_p = log1pf(__expf(p0));
        float lam_f = log1pf(__expf(p1));
        float sig2  = __fdividef(1.0f, 1.0f + __expf(-p2));
        float sig3  = __fdividef(1.0f, 1.0f + __expf(-p3));
        g_fnpc[0] = lam_p;
        g_fnpc[1] = lam_p * sig2;
        g_fnpc[2] = lam_f * (1.0f + sig3);
    }

    // kmax bucket table: bucket b covers U2 in (2^(b/8-6), 2^((b+1)/8-6)];
    // store count of u_k^2 <= upper edge (conservative: includes, never cuts).
    if (ij < 128) {
        int cnt;
        if (ij == 127) {
            cnt = NK;
        } else {
            float U2_hi = exp2f((float)(ij + 1) * 0.125f - 6.0f);
            cnt = 0;
            for (int k = 0; k < NK; k++) {
                float u = ogx[k];
                if (u * u <= U2_hi) cnt = k + 1;
            }
        }
        g_kmaxtab[ij] = cnt;
    }

    if (ij < NXg * NBg) {
        union { uint4 u; __half h[8]; } pk, fk;
#pragma unroll
        for (int f = 0; f < 8; f++) {
            pk.h[f] = __float2half_rn(c_E2[f] * pdf[f * (NXg * NBg) + ij]);
            fk.h[f] = __float2half_rn(ff[f * (NXg * NBg) + ij]);
        }
        reinterpret_cast<uint4*>(g_pdf_h)[ij] = pk.u;
        reinterpret_cast<uint4*>(g_ff_h )[ij] = fk.u;
    }
}

// ---------------------------------------------------------------------------
// Kernel 2: main — 4 lanes per event (k = sub + 4*i), bucket-table trip
// count, butterfly reduce, lane 0 applies prefactor.
// ---------------------------------------------------------------------------
__global__ __launch_bounds__(256)
void sidis_kernel(const float* __restrict__ ev,
                  const float* __restrict__ ogx,
                  const float* __restrict__ ogw,
                  float* __restrict__ out,
                  int n_events)
{
    __shared__ float s_u2[NK], s_lu[NK], s_w[NK];
    __shared__ int   s_km[128];
    int t = threadIdx.x;
    if (t < NK) {
        float u = ogx[t];
        s_u2[t] = u * u;
        s_lu[t] = __logf(u);
        s_w[t]  = ogw[t];
    }
    if (t < 128) s_km[t] = g_kmaxtab[t];
    __syncthreads();

    int gt  = blockIdx.x * blockDim.x + t;
    int n   = gt >> 2;          // event index
    int sub = gt & 3;           // lane within 4-lane group
    if (n >= n_events) return;

    const float LXMIN  = (float)LXMIN_D;
    const float LBMIN  = (float)LBMIN_D;
    const float XSCALE = (float)(255.0 / (0.0 - LXMIN_D));
    const float BSCALE = (float)(255.0 / (LBMAX_D - LBMIN_D));

    float4 e = __ldg(reinterpret_cast<const float4*>(ev) + n);
    float x = e.x, PhT = e.y, Q = e.z, z = e.w;

    float rz  = __fdividef(1.0f, z);
    float rP  = __fdividef(1.0f, PhT);
    float qT     = PhT * rz;
    float inv_qT = z * rP;
    float inv_z2 = rz * rz;
    float Q2  = Q * Q;

    float lx = __logf(x);
    float fx = fminf(fmaxf((lx - LXMIN) * XSCALE, 0.0f), 255.0f - 1e-4f);
    int   i0p = (int)fx;
    float txp = fx - (float)i0p;

    float lz = __logf(z);
    float fz = fminf(fmaxf((lz - LXMIN) * XSCALE, 0.0f), 255.0f - 1e-4f);
    int   i0f = (int)fz;
    float txf = fz - (float)i0f;

    float lQ2 = 2.0f * __logf(Q);
    float log_invqT = lz - __logf(PhT);

    float A = g_fnpc[0], B = g_fnpc[1], C = g_fnpc[2];
    float c = fmaf(0.12f, lQ2, A) - B * lx + C * inv_z2;

    float cq = c * inv_qT * inv_qT;           // arg_k = -cq * u_k^2

    // trip count via conservative bucket table
    float U2 = s_u2[0] + 36.0f * __fdividef(1.0f, cq);
    int b = (int)((__log2f(U2) + 6.0f) * 8.0f);
    b = min(max(b, 0), 127);
    int kmax = s_km[b];

    const __half* pbase = g_pdf_h + i0p * (NBg * 8);
    const __half* fbase = g_ff_h  + i0f * (NBg * 8);

    float acc = 0.0f;
#pragma unroll 2
    for (int k = sub; k < kmax; k += LPE) {
        float arg = -cq * s_u2[k];

        float lb = s_lu[k] + log_invqT;
        float fb = fminf(fmaxf((lb - LBMIN) * BSCALE, 0.0f), 255.0f - 1e-4f);
        int   j0 = (int)fb;
        float tb = fb - (float)j0;

        const uint4* pr0 = reinterpret_cast<const uint4*>(pbase + j0 * 8);
        const uint4* pr1 = reinterpret_cast<const uint4*>(pbase + NBg * 8 + j0 * 8);
        uint4 P00 = __ldg(pr0), P01 = __ldg(pr0 + 1);
        uint4 P10 = __ldg(pr1), P11 = __ldg(pr1 + 1);

        const uint4* fr0 = reinterpret_cast<const uint4*>(fbase + j0 * 8);
        const uint4* fr1 = reinterpret_cast<const uint4*>(fbase + NBg * 8 + j0 * 8);
        uint4 F00 = __ldg(fr0), F01 = __ldg(fr0 + 1);
        uint4 F10 = __ldg(fr1), F11 = __ldg(fr1 + 1);

        float4 pa0, pa1, pb0, pb1, pc0, pc1, pd0, pd1;
        h8_to_f(P00, pa0, pa1);  h8_to_f(P01, pb0, pb1);
        h8_to_f(P10, pc0, pc1);  h8_to_f(P11, pd0, pd1);

        float4 fa0, fa1, fb0, fb1, fc0, fc1, fd0, fd1;
        h8_to_f(F00, fa0, fa1);  h8_to_f(F01, fb0, fb1);
        h8_to_f(F10, fc0, fc1);  h8_to_f(F11, fd0, fd1);

        float4 pr0l = lerp4(pa0, pb0, tb);
        float4 pr0h = lerp4(pa1, pb1, tb);
        float4 pr1l = lerp4(pc0, pd0, tb);
        float4 pr1h = lerp4(pc1, pd1, tb);
        float4 pvl  = lerp4(pr0l, pr1l, txp);
        float4 pvh  = lerp4(pr0h, pr1h, txp);

        float4 fr0l = lerp4(fa0, fb0, tb);
        float4 fr0h = lerp4(fa1, fb1, tb);
        float4 fr1l = lerp4(fc0, fd0, tb);
        float4 fr1h = lerp4(fc1, fd1, tb);
        float4 fvl  = lerp4(fr0l, fr1l, txf);
        float4 fvh  = lerp4(fr0h, fr1h, txf);

        float s = pvl.x * fvl.x + pvl.y * fvl.y + pvl.z * fvl.z + pvl.w * fvl.w
                + pvh.x * fvh.x + pvh.y * fvh.y + pvh.z * fvh.z + pvh.w * fvh.w;

        acc = fmaf(s * s_w[k], __expf(arg), acc);
    }

    // reduce the 4 lanes of this event
    acc += __shfl_xor_sync(0xFFFFFFFFu, acc, 1);
    acc += __shfl_xor_sync(0xFFFFFFFFu, acc, 2);

    if (sub == 0) {
        float FUUT = acc * inv_qT * inv_qT;

        const float ALPHA0 = 0.00729735253f;
        const float L_ME2  = 15.1582899f;
        float rx = __fdividef(1.0f, x);
        float rQ = __fdividef(1.0f, Q);
        float lQme = lQ2 + L_ME2;
        float alpha = __fdividef(ALPHA0,
                      1.0f - (ALPHA0 / (3.0f * 3.14159265358979f)) * lQme);
        float gamma = 2.0f * 0.8803f * x * rQ;
        float y  = Q2 * rx * (1.0f / (140.0f - 0.8803f));
        float g2y2 = gamma * gamma * y * y;
        float epsn = 1.0f - y - 0.25f * g2y2;
        float epsd = 1.0f - y + 0.5f * y * y + 0.25f * g2y2;
        float eps  = __fdividef(epsn, epsd);
        float pre = 78.9568352f
                  * alpha * alpha * (z * z) * qT
                  * rx * (rQ * rQ * rQ)
                  * (y * y) * 0.5f * __fdividef(1.0f, 1.0f - eps)
                  * (1.0f + gamma * gamma * (0.5f * rx));

        out[n] = pre * FUUT;
    }
}

// ---------------------------------------------------------------------------
// kernel_launch
// Inputs: events (N,4), pdf (8,256,256), ff (8,256,256), ogata_x (64),
// ogata_w (64), fnp (4)
// ---------------------------------------------------------------------------
extern "C" void kernel_launch(void* const* d_in, const int* in_sizes, int n_in,
                              void* d_out, int out_size)
{
    const float* ev   = (const float*)d_in[0];
    const float* pdfg = (const float*)d_in[1];
    const float* ffg  = (const float*)d_in[2];
    const float* ogx  = (const float*)d_in[3];
    const float* ogw  = (const float*)d_in[4];
    const float* fnp  = (const float*)d_in[5];
    float* out = (float*)d_out;

    int n_events = in_sizes[0] / 4;

    prep_kernel<<<(NXg * NBg + 255) / 256, 256>>>(pdfg, ffg, ogx, fnp);

    int total_threads = n_events * LPE;
    int blocks = (total_threads + 255) / 256;
    sidis_kernel<<<blocks, 256>>>(ev, ogx, ogw, out, n_events);
}